// round 2
// baseline (speedup 1.0000x reference)
#include <cuda_runtime.h>
#include <cuda_bf16.h>
#include <cstdint>
#include <cstddef>

// ============================================================================
// PTQLinear: out[t,o] = scale[o] * sum_i x[t,i]*wq[o,i] + bias[o]
// T=8192, DIN=4096, DOUT=4096.
// Base compute_100 PTX only (no tcgen05): sm80-style pipelined mma.sync bf16.
// wq exact in bf16; x split into bf16 hi + lo residual; both accumulated into
// the same fp32 accumulators -> rel err ~1e-5.
// ============================================================================

#define K_TOKENS 8192
#define K_DIN    4096
#define K_DOUT   4096

// ---------------- static device scratch (no allocation allowed) ------------
__device__ __nv_bfloat16 g_W  [(size_t)K_DOUT  * K_DIN];
__device__ __nv_bfloat16 g_Xhi[(size_t)K_TOKENS * K_DIN];
__device__ __nv_bfloat16 g_Xlo[(size_t)K_TOKENS * K_DIN];

// ---------------- GEMM configuration ----------------------------------------
constexpr int TM = 128;              // CTA M tile
constexpr int TN = 256;              // CTA N tile
constexpr int KC = 32;               // K chunk (bf16 elements)
constexpr int NCHUNK = K_DIN / KC;   // 128
constexpr int STAGES = 4;

constexpr int ROWB   = 80;                       // padded row stride bytes (32 bf16 + 8 pad)
constexpr int A_TILE = TM * ROWB;                // 10240
constexpr int B_TILE = TN * ROWB;                // 20480
constexpr int STAGE_BYTES = 2 * A_TILE + B_TILE; // 40960
constexpr int CTRL = 2048;                       // scale + bias
constexpr int SMEM_BYTES = CTRL + STAGES * STAGE_BYTES;  // 165888

// ---------------- PTX helpers ------------------------------------------------
static __device__ __forceinline__ uint32_t smem_u32(const void* p) {
    return (uint32_t)__cvta_generic_to_shared(p);
}

static __device__ __forceinline__ void cp_async16(uint32_t dst, const void* src) {
    asm volatile("cp.async.cg.shared.global [%0], [%1], 16;\n"
                 :: "r"(dst), "l"(src));
}
static __device__ __forceinline__ void cp_commit() {
    asm volatile("cp.async.commit_group;\n" ::: "memory");
}

static __device__ __forceinline__ void ldmatrix_x4(uint32_t* r, uint32_t addr) {
    asm volatile("ldmatrix.sync.aligned.m8n8.x4.shared.b16 {%0,%1,%2,%3}, [%4];\n"
                 : "=r"(r[0]), "=r"(r[1]), "=r"(r[2]), "=r"(r[3]) : "r"(addr));
}

static __device__ __forceinline__ void mma_bf16(float* c, const uint32_t* a,
                                                const uint32_t* b) {
    asm volatile(
        "mma.sync.aligned.m16n8k16.row.col.f32.bf16.bf16.f32 "
        "{%0,%1,%2,%3}, {%4,%5,%6,%7}, {%8,%9}, {%0,%1,%2,%3};\n"
        : "+f"(c[0]), "+f"(c[1]), "+f"(c[2]), "+f"(c[3])
        : "r"(a[0]), "r"(a[1]), "r"(a[2]), "r"(a[3]), "r"(b[0]), "r"(b[1]));
}

// ---------------- preprocess kernels ------------------------------------------
__global__ void __launch_bounds__(256)
convert_w_kernel(const int* __restrict__ wq)
{
    size_t i = (size_t)blockIdx.x * 256 + threadIdx.x;   // over DOUT*DIN/4
    int4 v = reinterpret_cast<const int4*>(wq)[i];
    __nv_bfloat162 p0 = __floats2bfloat162_rn((float)v.x, (float)v.y);
    __nv_bfloat162 p1 = __floats2bfloat162_rn((float)v.z, (float)v.w);
    uint2 u;
    u.x = reinterpret_cast<uint32_t&>(p0);
    u.y = reinterpret_cast<uint32_t&>(p1);
    reinterpret_cast<uint2*>(g_W)[i] = u;
}

__global__ void __launch_bounds__(256)
split_x_kernel(const float* __restrict__ x)
{
    size_t i = (size_t)blockIdx.x * 256 + threadIdx.x;   // over TOKENS*DIN/4
    float4 v = reinterpret_cast<const float4*>(x)[i];
    __nv_bfloat16 h0 = __float2bfloat16_rn(v.x);
    __nv_bfloat16 h1 = __float2bfloat16_rn(v.y);
    __nv_bfloat16 h2 = __float2bfloat16_rn(v.z);
    __nv_bfloat16 h3 = __float2bfloat16_rn(v.w);
    float l0 = v.x - __bfloat162float(h0);
    float l1 = v.y - __bfloat162float(h1);
    float l2 = v.z - __bfloat162float(h2);
    float l3 = v.w - __bfloat162float(h3);
    __nv_bfloat162 hp0 = __halves2bfloat162(h0, h1);
    __nv_bfloat162 hp1 = __halves2bfloat162(h2, h3);
    __nv_bfloat162 lp0 = __floats2bfloat162_rn(l0, l1);
    __nv_bfloat162 lp1 = __floats2bfloat162_rn(l2, l3);
    uint2 uh, ul;
    uh.x = reinterpret_cast<uint32_t&>(hp0);
    uh.y = reinterpret_cast<uint32_t&>(hp1);
    ul.x = reinterpret_cast<uint32_t&>(lp0);
    ul.y = reinterpret_cast<uint32_t&>(lp1);
    reinterpret_cast<uint2*>(g_Xhi)[i] = uh;
    reinterpret_cast<uint2*>(g_Xlo)[i] = ul;
}

// ---------------- main GEMM kernel --------------------------------------------
__global__ void __launch_bounds__(256)
ptq_gemm_kernel(const float* __restrict__ scales,
                const float* __restrict__ bias,
                float* __restrict__ out)
{
    extern __shared__ char smem[];
    const uint32_t sbase = smem_u32(smem);

    const int tid  = threadIdx.x;
    const int wid  = tid >> 5;
    const int lane = tid & 31;
    const int wm   = wid >> 2;     // 0..1  (M band of 64)
    const int wn   = wid & 3;      // 0..3  (N band of 64)
    const int gid  = lane >> 2;    // mma group id
    const int tig  = lane & 3;     // thread-in-group

    const int n0 = blockIdx.x * TN;
    const int m0 = blockIdx.y * TM;

    float* s_scale = (float*)smem;           // 256 floats
    float* s_bias  = (float*)(smem + 1024);  // 256 floats
    s_scale[tid] = scales[n0 + tid];
    s_bias[tid]  = bias[n0 + tid];

    const uint32_t tiles = sbase + CTRL;

    // ---- per-thread cp.async source/dest (A: 512 16B units, B: 1024) ----
    const int ldr = tid >> 2;        // row 0..63
    const int ldc = tid & 3;         // 16B column 0..3
    const __nv_bfloat16* a_hi_src = g_Xhi + (size_t)(m0 + ldr) * K_DIN + ldc * 8;
    const __nv_bfloat16* a_lo_src = g_Xlo + (size_t)(m0 + ldr) * K_DIN + ldc * 8;
    const __nv_bfloat16* b_src    = g_W   + (size_t)(n0 + ldr) * K_DIN + ldc * 8;
    const uint32_t a_dst = tiles + ldr * ROWB + ldc * 16;
    const uint32_t b_dst = tiles + 2 * A_TILE + ldr * ROWB + ldc * 16;

    // ---- per-lane ldmatrix address bases (mt/ks/p-independent parts) ----
    const int mat = lane >> 3;       // which 8x8 matrix this lane addresses
    const int mrow = lane & 7;
    // A: mat0:(r+0,klo) mat1:(r+8,klo) mat2:(r+0,khi) mat3:(r+8,khi)
    const uint32_t a_base =
        (uint32_t)((wm * 64 + (mat & 1) * 8 + mrow) * ROWB + (mat >> 1) * 16);
    // B: mat0:(n+0,klo) mat1:(n+0,khi) mat2:(n+8,klo) mat3:(n+8,khi)
    const uint32_t b_base = (uint32_t)(2 * A_TILE +
        (wn * 64 + (mat >> 1) * 8 + mrow) * ROWB + (mat & 1) * 16);

    float acc[4][8][4];
#pragma unroll
    for (int mt = 0; mt < 4; ++mt)
#pragma unroll
        for (int nt = 0; nt < 8; ++nt)
#pragma unroll
            for (int q = 0; q < 4; ++q) acc[mt][nt][q] = 0.0f;

    __syncthreads();   // scale/bias visible; smem tiles free

    // ---- prologue: fill STAGES-1 stages ----
#pragma unroll
    for (int s = 0; s < STAGES - 1; ++s) {
        const int k0 = s * KC;
        const uint32_t stg = (uint32_t)(s * STAGE_BYTES);
        cp_async16(a_dst + stg,             a_hi_src + k0);
        cp_async16(a_dst + stg + 64 * ROWB, a_hi_src + k0 + (size_t)64 * K_DIN);
        cp_async16(a_dst + stg + A_TILE,             a_lo_src + k0);
        cp_async16(a_dst + stg + A_TILE + 64 * ROWB, a_lo_src + k0 + (size_t)64 * K_DIN);
#pragma unroll
        for (int i = 0; i < 4; ++i)
            cp_async16(b_dst + stg + i * 64 * ROWB, b_src + k0 + (size_t)(i * 64) * K_DIN);
        cp_commit();
    }

#pragma unroll 1
    for (int c = 0; c < NCHUNK; ++c) {
        asm volatile("cp.async.wait_group 2;\n" ::: "memory");
        __syncthreads();

        // issue loads for stage c+STAGES-1
        if (c + STAGES - 1 < NCHUNK) {
            const int k0 = (c + STAGES - 1) * KC;
            const uint32_t stg = (uint32_t)(((c + STAGES - 1) % STAGES) * STAGE_BYTES);
            cp_async16(a_dst + stg,             a_hi_src + k0);
            cp_async16(a_dst + stg + 64 * ROWB, a_hi_src + k0 + (size_t)64 * K_DIN);
            cp_async16(a_dst + stg + A_TILE,             a_lo_src + k0);
            cp_async16(a_dst + stg + A_TILE + 64 * ROWB, a_lo_src + k0 + (size_t)64 * K_DIN);
#pragma unroll
            for (int i = 0; i < 4; ++i)
                cp_async16(b_dst + stg + i * 64 * ROWB, b_src + k0 + (size_t)(i * 64) * K_DIN);
        }
        cp_commit();

        const uint32_t stg = tiles + (uint32_t)((c % STAGES) * STAGE_BYTES);

#pragma unroll
        for (int ks = 0; ks < 2; ++ks) {
            const uint32_t koff = ks * 32;   // 16 bf16 = 32B

            uint32_t bf[4][4];
#pragma unroll
            for (int p = 0; p < 4; ++p)      // ntile pair p -> ntiles 2p, 2p+1
                ldmatrix_x4(bf[p], stg + b_base + p * 16 * ROWB + koff);

            uint32_t af[4][4];
#pragma unroll
            for (int mt = 0; mt < 4; ++mt)   // A hi
                ldmatrix_x4(af[mt], stg + a_base + mt * 16 * ROWB + koff);
#pragma unroll
            for (int mt = 0; mt < 4; ++mt)
#pragma unroll
                for (int p = 0; p < 4; ++p) {
                    mma_bf16(acc[mt][2 * p],     af[mt], &bf[p][0]);
                    mma_bf16(acc[mt][2 * p + 1], af[mt], &bf[p][2]);
                }
#pragma unroll
            for (int mt = 0; mt < 4; ++mt)   // A lo
                ldmatrix_x4(af[mt], stg + a_base + A_TILE + mt * 16 * ROWB + koff);
#pragma unroll
            for (int mt = 0; mt < 4; ++mt)
#pragma unroll
                for (int p = 0; p < 4; ++p) {
                    mma_bf16(acc[mt][2 * p],     af[mt], &bf[p][0]);
                    mma_bf16(acc[mt][2 * p + 1], af[mt], &bf[p][2]);
                }
        }
    }

    // ---- epilogue: dequant + bias, direct stores ----
#pragma unroll
    for (int mt = 0; mt < 4; ++mt) {
        const int r0 = m0 + wm * 64 + mt * 16 + gid;
        float* o0 = out + (size_t)r0 * K_DOUT + n0;
        float* o1 = o0 + (size_t)8 * K_DOUT;
#pragma unroll
        for (int nt = 0; nt < 8; ++nt) {
            const int cl = wn * 64 + nt * 8 + tig * 2;
            const float2 sc = *(const float2*)(s_scale + cl);
            const float2 bs = *(const float2*)(s_bias + cl);
            float2 v0, v1;
            v0.x = acc[mt][nt][0] * sc.x + bs.x;
            v0.y = acc[mt][nt][1] * sc.y + bs.y;
            v1.x = acc[mt][nt][2] * sc.x + bs.x;
            v1.y = acc[mt][nt][3] * sc.y + bs.y;
            *(float2*)(o0 + cl) = v0;
            *(float2*)(o1 + cl) = v1;
        }
    }
}

// ---------------- launch -------------------------------------------------------
extern "C" void kernel_launch(void* const* d_in, const int* in_sizes, int n_in,
                              void* d_out, int out_size)
{
    (void)in_sizes; (void)n_in; (void)out_size;
    const float* x      = (const float*)d_in[0];
    const int*   wq     = (const int*)  d_in[1];
    const float* scales = (const float*)d_in[2];
    const float* bias   = (const float*)d_in[3];
    float*       out    = (float*)d_out;

    convert_w_kernel<<<(unsigned)((size_t)K_DOUT * K_DIN / 4 / 256), 256>>>(wq);
    split_x_kernel  <<<(unsigned)((size_t)K_TOKENS * K_DIN / 4 / 256), 256>>>(x);

    static int smem_set = 0;
    if (!smem_set) {
        cudaFuncSetAttribute(ptq_gemm_kernel,
                             cudaFuncAttributeMaxDynamicSharedMemorySize, SMEM_BYTES);
        smem_set = 1;
    }
    dim3 grid(K_DOUT / TN, K_TOKENS / TM);   // (16, 64)
    ptq_gemm_kernel<<<grid, 256, SMEM_BYTES>>>(scales, bias, out);
}

// round 3
// speedup vs baseline: 1.9265x; 1.9265x over previous
#include <cuda_runtime.h>
#include <cuda_fp16.h>
#include <cstdint>
#include <cstddef>

// ============================================================================
// PTQLinear: out[t,o] = scale[o] * sum_i x[t,i]*wq[o,i] + bias[o]
// T=8192, DIN=4096, DOUT=4096.
// Single-pass fp16 mma.sync (compute_100-legal): wq exact in fp16;
// x rounded to fp16 (aggregate rel err ~2.8e-4 < 1e-3). fp32 accumulators.
// ============================================================================

#define K_TOKENS 8192
#define K_DIN    4096
#define K_DOUT   4096

// ---------------- static device scratch (no allocation allowed) ------------
__device__ __half g_W[(size_t)K_DOUT  * K_DIN];
__device__ __half g_X[(size_t)K_TOKENS * K_DIN];

// ---------------- GEMM configuration ----------------------------------------
constexpr int TM = 128;              // CTA M tile
constexpr int TN = 256;              // CTA N tile
constexpr int KC = 64;               // K chunk (fp16 elements) = 128 B rows
constexpr int NCHUNK = K_DIN / KC;   // 64
constexpr int STAGES = 3;

constexpr int ROWB   = 144;                      // 128 B row + 16 B pad
constexpr int A_TILE = TM * ROWB;                // 18432
constexpr int B_TILE = TN * ROWB;                // 36864
constexpr int STAGE_BYTES = A_TILE + B_TILE;     // 55296
constexpr int CTRL = 2048;                       // scale + bias
constexpr int SMEM_BYTES = CTRL + STAGES * STAGE_BYTES;  // 167936

// ---------------- PTX helpers ------------------------------------------------
static __device__ __forceinline__ uint32_t smem_u32(const void* p) {
    return (uint32_t)__cvta_generic_to_shared(p);
}

static __device__ __forceinline__ void cp_async16(uint32_t dst, const void* src) {
    asm volatile("cp.async.cg.shared.global [%0], [%1], 16;\n"
                 :: "r"(dst), "l"(src));
}
static __device__ __forceinline__ void cp_commit() {
    asm volatile("cp.async.commit_group;\n" ::: "memory");
}

static __device__ __forceinline__ void ldmatrix_x4(uint32_t* r, uint32_t addr) {
    asm volatile("ldmatrix.sync.aligned.m8n8.x4.shared.b16 {%0,%1,%2,%3}, [%4];\n"
                 : "=r"(r[0]), "=r"(r[1]), "=r"(r[2]), "=r"(r[3]) : "r"(addr));
}

static __device__ __forceinline__ void mma_f16(float* c, const uint32_t* a,
                                               const uint32_t* b) {
    asm volatile(
        "mma.sync.aligned.m16n8k16.row.col.f32.f16.f16.f32 "
        "{%0,%1,%2,%3}, {%4,%5,%6,%7}, {%8,%9}, {%0,%1,%2,%3};\n"
        : "+f"(c[0]), "+f"(c[1]), "+f"(c[2]), "+f"(c[3])
        : "r"(a[0]), "r"(a[1]), "r"(a[2]), "r"(a[3]), "r"(b[0]), "r"(b[1]));
}

// ---------------- preprocess kernels ------------------------------------------
// 8 elements per thread: int32 weights -> exact fp16.
__global__ void __launch_bounds__(256)
convert_w_kernel(const int* __restrict__ wq)
{
    size_t i = (size_t)blockIdx.x * 256 + threadIdx.x;   // over DOUT*DIN/8
    const int4* p = reinterpret_cast<const int4*>(wq);
    int4 v0 = p[2 * i];
    int4 v1 = p[2 * i + 1];
    __half2 h0 = __floats2half2_rn((float)v0.x, (float)v0.y);
    __half2 h1 = __floats2half2_rn((float)v0.z, (float)v0.w);
    __half2 h2 = __floats2half2_rn((float)v1.x, (float)v1.y);
    __half2 h3 = __floats2half2_rn((float)v1.z, (float)v1.w);
    uint4 u;
    u.x = reinterpret_cast<uint32_t&>(h0);
    u.y = reinterpret_cast<uint32_t&>(h1);
    u.z = reinterpret_cast<uint32_t&>(h2);
    u.w = reinterpret_cast<uint32_t&>(h3);
    reinterpret_cast<uint4*>(g_W)[i] = u;
}

// 8 elements per thread: x fp32 -> fp16 (round-to-nearest).
__global__ void __launch_bounds__(256)
convert_x_kernel(const float* __restrict__ x)
{
    size_t i = (size_t)blockIdx.x * 256 + threadIdx.x;   // over TOKENS*DIN/8
    const float4* p = reinterpret_cast<const float4*>(x);
    float4 v0 = p[2 * i];
    float4 v1 = p[2 * i + 1];
    __half2 h0 = __floats2half2_rn(v0.x, v0.y);
    __half2 h1 = __floats2half2_rn(v0.z, v0.w);
    __half2 h2 = __floats2half2_rn(v1.x, v1.y);
    __half2 h3 = __floats2half2_rn(v1.z, v1.w);
    uint4 u;
    u.x = reinterpret_cast<uint32_t&>(h0);
    u.y = reinterpret_cast<uint32_t&>(h1);
    u.z = reinterpret_cast<uint32_t&>(h2);
    u.w = reinterpret_cast<uint32_t&>(h3);
    reinterpret_cast<uint4*>(g_X)[i] = u;
}

// ---------------- main GEMM kernel --------------------------------------------
__global__ void __launch_bounds__(256)
ptq_gemm_kernel(const float* __restrict__ scales,
                const float* __restrict__ bias,
                float* __restrict__ out)
{
    extern __shared__ char smem[];
    const uint32_t sbase = smem_u32(smem);

    const int tid  = threadIdx.x;
    const int wid  = tid >> 5;
    const int lane = tid & 31;
    const int wm   = wid >> 2;     // 0..1  (M band of 64)
    const int wn   = wid & 3;      // 0..3  (N band of 64)
    const int gid  = lane >> 2;    // mma group id
    const int tig  = lane & 3;     // thread-in-group

    const int n0 = blockIdx.x * TN;
    const int m0 = blockIdx.y * TM;

    float* s_scale = (float*)smem;           // 256 floats
    float* s_bias  = (float*)(smem + 1024);  // 256 floats
    s_scale[tid] = scales[n0 + tid];
    s_bias[tid]  = bias[n0 + tid];

    const uint32_t tiles = sbase + CTRL;

    // ---- per-thread cp.async mapping ----
    // A: 128 rows x 8 16B units = 1024 units, 4 per thread
    // B: 256 rows x 8 units     = 2048 units, 8 per thread
    const int a_row = tid >> 3;        // rows 0..31 (+32*i)
    const int a_c16 = tid & 7;
    const __half* a_src = g_X + (size_t)(m0 + a_row) * K_DIN + a_c16 * 8;
    const __half* b_src = g_W + (size_t)(n0 + a_row) * K_DIN + a_c16 * 8;
    const uint32_t a_dst = tiles + a_row * ROWB + a_c16 * 16;
    const uint32_t b_dst = tiles + A_TILE + a_row * ROWB + a_c16 * 16;

    // ---- per-lane ldmatrix base addresses ----
    const int mat  = lane >> 3;      // matrix index within x4
    const int mrow = lane & 7;
    // A mats: m0 rows+0 klo16B, m1 rows+8 klo, m2 rows+0 khi, m3 rows+8 khi
    const uint32_t a_base =
        (uint32_t)((wm * 64 + (mat & 1) * 8 + mrow) * ROWB + (mat >> 1) * 16);
    // B mats: m0 n+0 klo, m1 n+0 khi, m2 n+8 klo, m3 n+8 khi
    const uint32_t b_base = (uint32_t)(A_TILE +
        (wn * 64 + (mat >> 1) * 8 + mrow) * ROWB + (mat & 1) * 16);

    float acc[4][8][4];
#pragma unroll
    for (int mt = 0; mt < 4; ++mt)
#pragma unroll
        for (int nt = 0; nt < 8; ++nt)
#pragma unroll
            for (int q = 0; q < 4; ++q) acc[mt][nt][q] = 0.0f;

    __syncthreads();   // scale/bias visible

    // ---- prologue: fill STAGES-1 stages ----
#pragma unroll
    for (int s = 0; s < STAGES - 1; ++s) {
        const int k0 = s * KC;
        const uint32_t stg = (uint32_t)(s * STAGE_BYTES);
#pragma unroll
        for (int i = 0; i < 4; ++i)
            cp_async16(a_dst + stg + i * 32 * ROWB, a_src + k0 + (size_t)(i * 32) * K_DIN);
#pragma unroll
        for (int i = 0; i < 8; ++i)
            cp_async16(b_dst + stg + i * 32 * ROWB, b_src + k0 + (size_t)(i * 32) * K_DIN);
        cp_commit();
    }

#pragma unroll 1
    for (int c = 0; c < NCHUNK; ++c) {
        asm volatile("cp.async.wait_group %0;\n" :: "n"(STAGES - 2) : "memory");
        __syncthreads();

        // issue loads for stage c+STAGES-1
        if (c + STAGES - 1 < NCHUNK) {
            const int k0 = (c + STAGES - 1) * KC;
            const uint32_t stg = (uint32_t)(((c + STAGES - 1) % STAGES) * STAGE_BYTES);
#pragma unroll
            for (int i = 0; i < 4; ++i)
                cp_async16(a_dst + stg + i * 32 * ROWB, a_src + k0 + (size_t)(i * 32) * K_DIN);
#pragma unroll
            for (int i = 0; i < 8; ++i)
                cp_async16(b_dst + stg + i * 32 * ROWB, b_src + k0 + (size_t)(i * 32) * K_DIN);
        }
        cp_commit();

        const uint32_t stg = tiles + (uint32_t)((c % STAGES) * STAGE_BYTES);

#pragma unroll
        for (int ks = 0; ks < 4; ++ks) {     // 4 x k16 per chunk
            const uint32_t koff = ks * 32;   // 16 fp16 = 32 B

            uint32_t bf[4][4];
#pragma unroll
            for (int p = 0; p < 4; ++p)      // ntile pair p -> ntiles 2p, 2p+1
                ldmatrix_x4(bf[p], stg + b_base + p * 16 * ROWB + koff);

            uint32_t af[4][4];
#pragma unroll
            for (int mt = 0; mt < 4; ++mt)
                ldmatrix_x4(af[mt], stg + a_base + mt * 16 * ROWB + koff);

#pragma unroll
            for (int mt = 0; mt < 4; ++mt)
#pragma unroll
                for (int p = 0; p < 4; ++p) {
                    mma_f16(acc[mt][2 * p],     af[mt], &bf[p][0]);
                    mma_f16(acc[mt][2 * p + 1], af[mt], &bf[p][2]);
                }
        }
    }

    // ---- epilogue: dequant + bias, direct stores ----
#pragma unroll
    for (int mt = 0; mt < 4; ++mt) {
        const int r0 = m0 + wm * 64 + mt * 16 + gid;
        float* o0 = out + (size_t)r0 * K_DOUT + n0;
        float* o1 = o0 + (size_t)8 * K_DOUT;
#pragma unroll
        for (int nt = 0; nt < 8; ++nt) {
            const int cl = wn * 64 + nt * 8 + tig * 2;
            const float2 sc = *(const float2*)(s_scale + cl);
            const float2 bs = *(const float2*)(s_bias + cl);
            float2 v0, v1;
            v0.x = acc[mt][nt][0] * sc.x + bs.x;
            v0.y = acc[mt][nt][1] * sc.y + bs.y;
            v1.x = acc[mt][nt][2] * sc.x + bs.x;
            v1.y = acc[mt][nt][3] * sc.y + bs.y;
            *(float2*)(o0 + cl) = v0;
            *(float2*)(o1 + cl) = v1;
        }
    }
}

// ---------------- launch -------------------------------------------------------
extern "C" void kernel_launch(void* const* d_in, const int* in_sizes, int n_in,
                              void* d_out, int out_size)
{
    (void)in_sizes; (void)n_in; (void)out_size;
    const float* x      = (const float*)d_in[0];
    const int*   wq     = (const int*)  d_in[1];
    const float* scales = (const float*)d_in[2];
    const float* bias   = (const float*)d_in[3];
    float*       out    = (float*)d_out;

    convert_w_kernel<<<(unsigned)((size_t)K_DOUT  * K_DIN / 8 / 256), 256>>>(wq);
    convert_x_kernel<<<(unsigned)((size_t)K_TOKENS * K_DIN / 8 / 256), 256>>>(x);

    cudaFuncSetAttribute(ptq_gemm_kernel,
                         cudaFuncAttributeMaxDynamicSharedMemorySize, SMEM_BYTES);
    dim3 grid(K_DOUT / TN, K_TOKENS / TM);   // (16, 64)
    ptq_gemm_kernel<<<grid, 256, SMEM_BYTES>>>(scales, bias, out);
}